// round 15
// baseline (speedup 1.0000x reference)
#include <cuda_runtime.h>
#include <math.h>

// ---------------- device scratch (no allocations allowed) ----------------
static __device__ float         g_part[800 * 8];
static __device__ float         g_sums[800];
static __device__ float         g_gate[800];
static __device__ int           g_chan[800];
static __device__ unsigned int  g_conv_ctr   = 0;
static __device__ unsigned int  g_gather_ctr = 0;
static __device__ unsigned int  g_exit_ctr   = 0;
static __device__ unsigned int  g_map_cnt[800];
static __device__ unsigned int  g_batch_cnt[32];
static __device__ volatile int  g_batch_ready[32];

// Fast exact-form GELU: 0.5*h*(1+erf(h/sqrt(2))) with Abramowitz-Stegun
// 7.1.25 3-term erf (max abs err ~2.5e-5; s-gap safety margin ~300x).
__device__ __forceinline__ float fast_gelu(float h)
{
    const float az = fabsf(h) * 0.7071067811865476f;
    const float t  = __fdividef(1.0f, fmaf(0.47047f, az, 1.0f));
    float p = fmaf(0.7478556f, t, -0.0958798f);
    p = fmaf(p, t, 0.3480242f);
    const float ex = __expf(-0.5f * h * h);
    float er = fmaf(-p * t, ex, 1.0f);
    er = copysignf(er, h);
    return 0.5f * h * (1.0f + er);
}

// Warp-local MLP + sigmoid + gate + stable top-k for one batch.
// __noinline__: keeps its registers out of the conv loop's allocation.
__device__ __noinline__ void warp_mlp(int bb, int lane, float* sc,
                                      const float* __restrict__ fc1w,
                                      const float* __restrict__ fc1b,
                                      const float* __restrict__ fc2w,
                                      const float* __restrict__ fc2b,
                                      float* __restrict__ out_idx)
{
    __threadfence();    // acquire g_sums written by other warps
    if (lane < 25) sc[lane] = g_sums[bb * 25 + lane] * (1.0f / 63504.0f);
    __syncwarp();
    #pragma unroll
    for (int rep = 0; rep < 2; rep++) {
        const int j = lane + rep * 32;
        if (j < 50) {
            float v = __ldg(fc1b + j);
            #pragma unroll
            for (int cc = 0; cc < 25; cc++)
                v = fmaf(sc[cc], __ldg(fc1w + j * 25 + cc), v);
            sc[25 + j] = v > 0.f ? v : 0.f;
        }
    }
    __syncwarp();
    if (lane < 25) {
        float z = __ldg(fc2b + lane);
        #pragma unroll
        for (int j = 0; j < 50; j++)
            z = fmaf(sc[25 + j], __ldg(fc2w + lane * 50 + j), z);
        sc[lane] = 1.0f / (1.0f + expf(-z));
    }
    __syncwarp();
    if (lane < 25) {
        const float sv = sc[lane];
        int rank = 0;
        #pragma unroll
        for (int o = 0; o < 25; o++) {
            const float ov = sc[o];
            rank += (ov > sv) || (ov == sv && o < lane);
        }
        const float s2 = sv * sv;
        g_chan[bb * 25 + rank]  = lane;
        g_gate[bb * 25 + rank]  = s2 / (s2 + 1e-8f);
        out_idx[bb * 25 + rank] = (float)lane;
        __threadfence();    // release before ready flag
    }
    __syncwarp();
    if (lane == 0) g_batch_ready[bb] = 1;
}

// =========================================================================
// Persistent warp-autonomous mega-kernel, TWO-PHASE (R12 structure).
// Conv weights live in per-warp SMEM (volatile broadcast LDS) to cut regs
// to ~80 -> 3 CTAs/SM (24 warps) for issue-slot coverage; software-
// pipelined rows; fast 3-term-erf GELU.
// =========================================================================
__global__ __launch_bounds__(256, 3)
void mega_kernel(const float* __restrict__ x,
                 const float* __restrict__ w7,
                 const float* __restrict__ b7,
                 const float* __restrict__ w3,
                 const float* __restrict__ fc1w,
                 const float* __restrict__ fc1b,
                 const float* __restrict__ fc2w,
                 const float* __restrict__ fc2b,
                 float* __restrict__ out)
{
    __shared__ float wsch[8][80];     // per-warp MLP scratch
    __shared__ float wsw[8][52];      // per-warp conv weights (49, padded)
    const int lane = threadIdx.x & 31;
    const int wid  = threadIdx.x >> 5;
    float* sc = wsch[wid];
    float* __restrict__ out_idx = out + 52428800ull;

    // ===================== phase 1: conv warp-units =====================
    while (true) {
        int uc;
        if (lane == 0) uc = (int)atomicAdd(&g_conv_ctr, 1u);
        uc = __shfl_sync(0xffffffffu, uc, 0);
        if (uc >= 6400) break;

        const int m    = uc >> 3;       // map (batch-major order)
        const int sub  = uc & 7;
        const int band = sub >> 1;
        const int half = sub & 1;
        const int c    = m % 25;
        const int b    = m / 25;
        const int cg   = half * 32 + lane;   // 0..63, active < 63

        // stage this unit's weights into per-warp smem
        for (int k = lane; k < 49; k += 32)
            wsw[wid][k] = __ldg(w7 + c * 49 + k);
        __syncwarp();

        float gsum = 0.f;

        if (cg < 63) {
            volatile const float* vw = wsw[wid];   // broadcast LDS, stays in smem
            const float bias = __ldg(b7 + c);

            float M0 = 0.f, M1 = 0.f, M2 = 0.f;
            #pragma unroll
            for (int a = 0; a < 3; a++) {
                const float v0 = __ldg(w3 + c * 9 + a * 3 + 0);
                const float v1 = __ldg(w3 + c * 9 + a * 3 + 1);
                const float v2 = __ldg(w3 + c * 9 + a * 3 + 2);
                M0 += v0 + v1; M1 += v0 + v1 + v2; M2 += v1 + v2;
            }
            const int q0 = cg * 4;
            float wv1[4];
            #pragma unroll
            for (int t = 0; t < 4; t++) {
                const int q   = q0 + t;
                const int cat = (q == 0) ? 0 : ((q == 251) ? 2 : 1);
                wv1[t] = (cat == 0) ? M0 : ((cat == 2) ? M2 : M1);
            }

            const bool okL  = (q0 > 0);
            const bool okR  = (q0 + 8 < 256);
            const int  offL = okL ? (q0 - 1) : 0;
            const int  offR = okR ? (q0 + 8) : 255;
            const int  lo   = band * 63;              // lo % 7 == 0
            const float* __restrict__ xm = x + (size_t)m * 65536;

            float buf[10];
            {   // prologue: row lo-1
                const int  r   = lo - 1;
                const bool rok = (r >= 0);
                const float* __restrict__ row = xm + (rok ? r : 0) * 256;
                float  xl = row[offL];
                float4 v0 = *reinterpret_cast<const float4*>(row + q0);
                float4 v1 = *reinterpret_cast<const float4*>(row + q0 + 4);
                float  xr = row[offR];
                buf[0] = (rok && okL) ? xl : 0.f;
                buf[1] = rok ? v0.x : 0.f;  buf[2] = rok ? v0.y : 0.f;
                buf[3] = rok ? v0.z : 0.f;  buf[4] = rok ? v0.w : 0.f;
                buf[5] = rok ? v1.x : 0.f;  buf[6] = rok ? v1.y : 0.f;
                buf[7] = rok ? v1.z : 0.f;  buf[8] = rok ? v1.w : 0.f;
                buf[9] = (rok && okR) ? xr : 0.f;
            }

            float acc[7][4];
            #pragma unroll
            for (int s = 0; s < 7; s++)
                #pragma unroll
                for (int t = 0; t < 4; t++) acc[s][t] = 0.f;

            for (int it = 0; it < 10; ++it) {
                #pragma unroll
                for (int u = 0; u < 7; u++) {
                    const int r = lo - 1 + it * 7 + u;   // row in buf

                    // issue next-row loads (hidden under FMA block)
                    const int  rn   = r + 1;
                    const bool rokn = ((unsigned)rn < 256u);
                    const int  rcn  = rokn ? rn : 255;
                    const float* __restrict__ rowp = xm + rcn * 256;
                    float  nxl = rowp[offL];
                    float4 nv0 = *reinterpret_cast<const float4*>(rowp + q0);
                    float4 nv1 = *reinterpret_cast<const float4*>(rowp + q0 + 4);
                    float  nxr = rowp[offR];

                    // 196 FMAs on buf (row r), weights via broadcast LDS
                    #pragma unroll
                    for (int a = 0; a < 7; a++) {
                        const int s = (u - a + 7) % 7;
                        #pragma unroll
                        for (int dx = 0; dx < 7; dx++) {
                            const float wk = vw[a * 7 + dx];
                            acc[s][0] = fmaf(buf[dx],     wk, acc[s][0]);
                            acc[s][1] = fmaf(buf[dx + 1], wk, acc[s][1]);
                            acc[s][2] = fmaf(buf[dx + 2], wk, acc[s][2]);
                            acc[s][3] = fmaf(buf[dx + 3], wk, acc[s][3]);
                        }
                    }

                    // retire out row i = r-5, slot (u+1)%7
                    {
                        const int  off   = it * 7 + u - 6;
                        const int  sret  = (u + 1) % 7;
                        const bool offok = (off >= 0) && (off <= 62);
                        const int  i     = lo + off;
                        const bool edge  = (i == 0) || (i == 251);  // warp-uniform

                        float wsv[4];
                        #pragma unroll
                        for (int t = 0; t < 4; t++) wsv[t] = wv1[t];
                        if (edge) {
                            // cold path: 2 of 252 rows
                            const int a0 = (i == 0) ? 0 : 1;
                            float C0 = 0.f, C1 = 0.f, C2 = 0.f;
                            #pragma unroll
                            for (int a = 0; a < 2; a++) {
                                const float v0 = __ldg(w3 + c * 9 + (a0 + a) * 3 + 0);
                                const float v1 = __ldg(w3 + c * 9 + (a0 + a) * 3 + 1);
                                const float v2 = __ldg(w3 + c * 9 + (a0 + a) * 3 + 2);
                                C0 += v0 + v1; C1 += v0 + v1 + v2; C2 += v1 + v2;
                            }
                            #pragma unroll
                            for (int t = 0; t < 4; t++) {
                                const int q   = q0 + t;
                                const int cat = (q == 0) ? 0 : ((q == 251) ? 2 : 1);
                                wsv[t] = (cat == 0) ? C0 : ((cat == 2) ? C2 : C1);
                            }
                        }
                        #pragma unroll
                        for (int t = 0; t < 4; t++) {
                            const float h  = acc[sret][t] + bias;
                            const float gl = fast_gelu(h);
                            const float ws = offok ? wsv[t] : 0.f;
                            gsum = fmaf(gl, ws, gsum);
                            acc[sret][t] = 0.f;
                        }
                    }

                    // commit prefetch
                    buf[0] = (rokn && okL) ? nxl : 0.f;
                    buf[1] = rokn ? nv0.x : 0.f;  buf[2] = rokn ? nv0.y : 0.f;
                    buf[3] = rokn ? nv0.z : 0.f;  buf[4] = rokn ? nv0.w : 0.f;
                    buf[5] = rokn ? nv1.x : 0.f;  buf[6] = rokn ? nv1.y : 0.f;
                    buf[7] = rokn ? nv1.z : 0.f;  buf[8] = rokn ? nv1.w : 0.f;
                    buf[9] = (rokn && okR) ? nxr : 0.f;
                }
            }
        }

        // warp reduce (fixed order -> deterministic)
        #pragma unroll
        for (int o = 16; o; o >>= 1)
            gsum += __shfl_xor_sync(0xffffffffu, gsum, o);

        int mlp_b = -1;
        if (lane == 0) {
            g_part[uc] = gsum;
            __threadfence();
            if (atomicAdd(&g_map_cnt[m], 1u) == 7u) {
                __threadfence();               // acquire other warps' partials
                float s = 0.f;
                #pragma unroll
                for (int k = 0; k < 8; k++) s += g_part[m * 8 + k];  // fixed order
                g_sums[m] = s;
                __threadfence();
                if (atomicAdd(&g_batch_cnt[b], 1u) == 24u) mlp_b = b;
            }
        }
        mlp_b = __shfl_sync(0xffffffffu, mlp_b, 0);
        if (mlp_b >= 0)
            warp_mlp(mlp_b, lane, sc, fc1w, fc1b, fc2w, fc2b, out_idx);
    }

    // ===================== phase 2: gather warp-units =====================
    // 6400 units = 32 batches x 25 maps x 8 octants, batch-ordered.
    while (true) {
        int g;
        if (lane == 0) g = (int)atomicAdd(&g_gather_ctr, 1u);
        g = __shfl_sync(0xffffffffu, g, 0);
        if (g >= 6400) break;
        const int b   = g / 200;
        const int rem = g % 200;
        const int r   = rem >> 3;
        const int oct = rem & 7;

        if (lane == 0) {
            while (g_batch_ready[b] == 0) __nanosleep(64);
        }
        __syncwarp();
        __threadfence();   // acquire gate/chan

        const int   ch = g_chan[b * 25 + r];
        const float gt = g_gate[b * 25 + r];

        const float4* __restrict__ src =
            reinterpret_cast<const float4*>(x + ((size_t)b * 25 + ch) * 65536);
        float* dbase;
        if (r < 10) dbase = out + ((size_t)b * 10 + r) * 65536;
        else        dbase = out + 20971520ull + ((size_t)b * 15 + (r - 10)) * 65536;
        float4* __restrict__ dst = reinterpret_cast<float4*>(dbase);

        const int base = oct * 2048 + lane;   // 2048 float4 per octant
        #pragma unroll
        for (int blk = 0; blk < 8; blk++) {
            float4 v[8];
            #pragma unroll
            for (int k = 0; k < 8; k++)
                v[k] = __ldcs(&src[base + (blk * 8 + k) * 32]);
            #pragma unroll
            for (int k = 0; k < 8; k++) {
                v[k].x *= gt; v[k].y *= gt; v[k].z *= gt; v[k].w *= gt;
                __stcs(&dst[base + (blk * 8 + k) * 32], v[k]);
            }
        }
    }

    // ===================== exit: last warp resets queues =====================
    {
        int is_last = 0;
        if (lane == 0) {
            __threadfence();
            unsigned v = atomicAdd(&g_exit_ctr, 1u);
            is_last = (v == gridDim.x * 8u - 1u);
        }
        is_last = __shfl_sync(0xffffffffu, is_last, 0);
        if (is_last) {
            for (int i = lane; i < 800; i += 32) g_map_cnt[i] = 0;
            g_batch_cnt[lane]   = 0;            // lane < 32
            g_batch_ready[lane] = 0;
            if (lane == 0) {
                g_conv_ctr   = 0;
                g_gather_ctr = 0;
                g_exit_ctr   = 0;
            }
            __threadfence();
        }
    }
}

// =========================================================================
extern "C" void kernel_launch(void* const* d_in, const int* in_sizes, int n_in,
                              void* d_out, int out_size)
{
    const float* x    = (const float*)d_in[0];
    const float* w7   = (const float*)d_in[1];
    const float* b7   = (const float*)d_in[2];
    const float* w3   = (const float*)d_in[3];
    const float* fc1w = (const float*)d_in[4];
    const float* fc1b = (const float*)d_in[5];
    const float* fc2w = (const float*)d_in[6];
    const float* fc2b = (const float*)d_in[7];
    float* out = (float*)d_out;

    mega_kernel<<<444, 256>>>(x, w7, b7, w3, fc1w, fc1b, fc2w, fc2b, out);
}

// round 16
// speedup vs baseline: 1.3795x; 1.3795x over previous
#include <cuda_runtime.h>
#include <math.h>

// ---------------- device scratch (no allocations allowed) ----------------
static __device__ float         g_part[800 * 8];
static __device__ float         g_sums[800];
static __device__ float         g_gate[800];
static __device__ int           g_chan[800];
static __device__ unsigned int  g_conv_ctr   = 0;
static __device__ unsigned int  g_gather_ctr = 0;
static __device__ unsigned int  g_exit_ctr   = 0;
static __device__ unsigned int  g_map_cnt[800];
static __device__ unsigned int  g_batch_cnt[32];
static __device__ volatile int  g_batch_ready[32];

// Fast exact-form GELU: A&S 7.1.25 3-term erf (max abs err ~2.5e-5;
// s-gap safety margin ~300x -- validated rel_err 0.0 in R15).
__device__ __forceinline__ float fast_gelu(float h)
{
    const float az = fabsf(h) * 0.7071067811865476f;
    const float t  = __fdividef(1.0f, fmaf(0.47047f, az, 1.0f));
    float p = fmaf(0.7478556f, t, -0.0958798f);
    p = fmaf(p, t, 0.3480242f);
    const float ex = __expf(-0.5f * h * h);
    float er = fmaf(-p * t, ex, 1.0f);
    er = copysignf(er, h);
    return 0.5f * h * (1.0f + er);
}

// Warp-local MLP + sigmoid + gate + stable top-k for one batch.
__device__ __forceinline__ void warp_mlp(int bb, int lane, float* sc,
                                         const float* __restrict__ fc1w,
                                         const float* __restrict__ fc1b,
                                         const float* __restrict__ fc2w,
                                         const float* __restrict__ fc2b,
                                         float* __restrict__ out_idx)
{
    __threadfence();    // acquire g_sums written by other warps
    if (lane < 25) sc[lane] = g_sums[bb * 25 + lane] * (1.0f / 63504.0f);
    __syncwarp();
    #pragma unroll
    for (int rep = 0; rep < 2; rep++) {
        const int j = lane + rep * 32;
        if (j < 50) {
            float v = __ldg(fc1b + j);
            #pragma unroll
            for (int cc = 0; cc < 25; cc++)
                v = fmaf(sc[cc], __ldg(fc1w + j * 25 + cc), v);
            sc[25 + j] = v > 0.f ? v : 0.f;
        }
    }
    __syncwarp();
    if (lane < 25) {
        float z = __ldg(fc2b + lane);
        #pragma unroll
        for (int j = 0; j < 50; j++)
            z = fmaf(sc[25 + j], __ldg(fc2w + lane * 50 + j), z);
        sc[lane] = 1.0f / (1.0f + expf(-z));
    }
    __syncwarp();
    if (lane < 25) {
        const float sv = sc[lane];
        int rank = 0;
        #pragma unroll
        for (int o = 0; o < 25; o++) {
            const float ov = sc[o];
            rank += (ov > sv) || (ov == sv && o < lane);
        }
        const float s2 = sv * sv;
        g_chan[bb * 25 + rank]  = lane;
        g_gate[bb * 25 + rank]  = s2 / (s2 + 1e-8f);
        out_idx[bb * 25 + rank] = (float)lane;
        __threadfence();    // release before ready flag
    }
    __syncwarp();
    if (lane == 0) g_batch_ready[bb] = 1;
}

// ---- conv inner-loop macros (registers: w[49], buf[10], acc[7][4]) ----
#define ISSUE_LOADS(RN)                                                    \
    const int  rn   = (RN);                                                \
    const bool rokn = ((unsigned)rn < 256u);                               \
    const int  rcn  = rokn ? rn : (rn < 0 ? 0 : 255);                      \
    const float* __restrict__ rowp = xm + rcn * 256;                       \
    const float  nxl = rowp[offL];                                         \
    const float4 nv0 = *reinterpret_cast<const float4*>(rowp + q0);        \
    const float4 nv1 = *reinterpret_cast<const float4*>(rowp + q0 + 4);    \
    const float  nxr = rowp[offR];

#define COMMIT_BUF()                                                       \
    buf[0] = (rokn && okL) ? nxl : 0.f;                                    \
    buf[1] = rokn ? nv0.x : 0.f;  buf[2] = rokn ? nv0.y : 0.f;             \
    buf[3] = rokn ? nv0.z : 0.f;  buf[4] = rokn ? nv0.w : 0.f;             \
    buf[5] = rokn ? nv1.x : 0.f;  buf[6] = rokn ? nv1.y : 0.f;             \
    buf[7] = rokn ? nv1.z : 0.f;  buf[8] = rokn ? nv1.w : 0.f;             \
    buf[9] = (rokn && okR) ? nxr : 0.f;

#define TAP_ROW(S, A)                                                      \
    _Pragma("unroll")                                                      \
    for (int dx = 0; dx < 7; dx++) {                                       \
        const float wk = w[(A) * 7 + dx];                                  \
        acc[S][0] = fmaf(buf[dx],     wk, acc[S][0]);                      \
        acc[S][1] = fmaf(buf[dx + 1], wk, acc[S][1]);                      \
        acc[S][2] = fmaf(buf[dx + 2], wk, acc[S][2]);                      \
        acc[S][3] = fmaf(buf[dx + 3], wk, acc[S][3]);                      \
    }

// =========================================================================
// Persistent warp-autonomous mega-kernel, two-phase (R12 structure).
// Conv ring loop PEELED into warmup(7)/main(56)/tail(6): only useful taps
// are issued (441 tap-rows vs 490, -10% FMAs); main-loop retire needs no
// validity/edge guards. Register weights; software-pipelined row loads.
// =========================================================================
__global__ __launch_bounds__(256, 2)
void mega_kernel(const float* __restrict__ x,
                 const float* __restrict__ w7,
                 const float* __restrict__ b7,
                 const float* __restrict__ w3,
                 const float* __restrict__ fc1w,
                 const float* __restrict__ fc1b,
                 const float* __restrict__ fc2w,
                 const float* __restrict__ fc2b,
                 float* __restrict__ out)
{
    __shared__ float wsch[8][80];
    const int lane = threadIdx.x & 31;
    const int wid  = threadIdx.x >> 5;
    float* sc = wsch[wid];
    float* __restrict__ out_idx = out + 52428800ull;

    // ===================== phase 1: conv warp-units =====================
    while (true) {
        int uc;
        if (lane == 0) uc = (int)atomicAdd(&g_conv_ctr, 1u);
        uc = __shfl_sync(0xffffffffu, uc, 0);
        if (uc >= 6400) break;

        const int m    = uc >> 3;       // map (batch-major order)
        const int sub  = uc & 7;
        const int band = sub >> 1;
        const int half = sub & 1;
        const int c    = m % 25;
        const int b    = m / 25;
        const int cg   = half * 32 + lane;   // 0..63, active < 63

        float gsum = 0.f;

        if (cg < 63) {
            float w[49];
            #pragma unroll
            for (int k = 0; k < 49; k++) w[k] = __ldg(w7 + c * 49 + k);
            const float bias = __ldg(b7 + c);

            float M0 = 0.f, M1 = 0.f, M2 = 0.f;
            #pragma unroll
            for (int a = 0; a < 3; a++) {
                const float v0 = __ldg(w3 + c * 9 + a * 3 + 0);
                const float v1 = __ldg(w3 + c * 9 + a * 3 + 1);
                const float v2 = __ldg(w3 + c * 9 + a * 3 + 2);
                M0 += v0 + v1; M1 += v0 + v1 + v2; M2 += v1 + v2;
            }
            const int q0 = cg * 4;
            float wv1[4];
            #pragma unroll
            for (int t = 0; t < 4; t++) {
                const int q   = q0 + t;
                const int cat = (q == 0) ? 0 : ((q == 251) ? 2 : 1);
                wv1[t] = (cat == 0) ? M0 : ((cat == 2) ? M2 : M1);
            }

            const bool okL  = (q0 > 0);
            const bool okR  = (q0 + 8 < 256);
            const int  offL = okL ? (q0 - 1) : 0;
            const int  offR = okR ? (q0 + 8) : 255;
            const int  lo   = band * 63;
            const float* __restrict__ xm = x + (size_t)m * 65536;

            float buf[10];
            {   // prologue: row lo-1 into buf
                ISSUE_LOADS(lo - 1)
                COMMIT_BUF()
            }

            float acc[7][4];
            #pragma unroll
            for (int s = 0; s < 7; s++)
                #pragma unroll
                for (int t = 0; t < 4; t++) acc[s][t] = 0.f;

            // ---- warmup: j=0..6, taps a<=j (only outputs >= lo) ----
            #pragma unroll
            for (int j = 0; j <= 6; j++) {
                ISSUE_LOADS(lo + j)            // next row for iteration j+1
                #pragma unroll
                for (int a = 0; a <= j; a++) {
                    TAP_ROW((j - a) % 7, a)
                }
                if (j == 6) {
                    // retire output i = lo (slot 0); edge iff lo == 0
                    float wsv[4];
                    #pragma unroll
                    for (int t = 0; t < 4; t++) wsv[t] = wv1[t];
                    if (lo == 0) {
                        float C0 = 0.f, C1 = 0.f, C2 = 0.f;
                        #pragma unroll
                        for (int a = 0; a < 2; a++) {
                            const float v0 = __ldg(w3 + c * 9 + a * 3 + 0);
                            const float v1 = __ldg(w3 + c * 9 + a * 3 + 1);
                            const float v2 = __ldg(w3 + c * 9 + a * 3 + 2);
                            C0 += v0 + v1; C1 += v0 + v1 + v2; C2 += v1 + v2;
                        }
                        #pragma unroll
                        for (int t = 0; t < 4; t++) {
                            const int q   = q0 + t;
                            const int cat = (q == 0) ? 0 : ((q == 251) ? 2 : 1);
                            wsv[t] = (cat == 0) ? C0 : ((cat == 2) ? C2 : C1);
                        }
                    }
                    #pragma unroll
                    for (int t = 0; t < 4; t++) {
                        gsum = fmaf(fast_gelu(acc[0][t] + bias), wsv[t], gsum);
                        acc[0][t] = 0.f;
                    }
                }
                COMMIT_BUF()
            }

            // ---- main: j=7..62 (it=0..7, u=0..6), full taps,
            //      retire off=j-6 in [1,56] -> always valid, never edge ----
            for (int it = 0; it < 8; ++it) {
                #pragma unroll
                for (int u = 0; u < 7; u++) {
                    ISSUE_LOADS(lo + 7 + it * 7 + u)
                    #pragma unroll
                    for (int a = 0; a < 7; a++) {
                        TAP_ROW((u - a + 7) % 7, a)
                    }
                    {
                        const int sret = (u + 1) % 7;
                        #pragma unroll
                        for (int t = 0; t < 4; t++) {
                            gsum = fmaf(fast_gelu(acc[sret][t] + bias),
                                        wv1[t], gsum);
                            acc[sret][t] = 0.f;
                        }
                    }
                    COMMIT_BUF()
                }
            }

            // ---- tail: j=63+d, d=0..5; taps a>=d+1 (outputs <= lo+62);
            //      retire off=57+d; edge iff i==251 (lo==189 && d==5) ----
            #pragma unroll
            for (int d = 0; d < 6; d++) {
                if (d < 5) {
                    ISSUE_LOADS(lo + 63 + d)
                    #pragma unroll
                    for (int a = d + 1; a < 7; a++) {
                        TAP_ROW((d - a + 7) % 7, a)
                    }
                    {
                        const int sret = (d + 1) % 7;
                        #pragma unroll
                        for (int t = 0; t < 4; t++) {
                            gsum = fmaf(fast_gelu(acc[sret][t] + bias),
                                        wv1[t], gsum);
                            acc[sret][t] = 0.f;
                        }
                    }
                    COMMIT_BUF()
                } else {
                    // d == 5: last iteration, no prefetch
                    #pragma unroll
                    for (int a = 6; a < 7; a++) {
                        TAP_ROW((d - a + 7) % 7, a)
                    }
                    const int  sret = (d + 1) % 7;    // 6
                    const int  i    = lo + 62;
                    float wsv[4];
                    #pragma unroll
                    for (int t = 0; t < 4; t++) wsv[t] = wv1[t];
                    if (i == 251) {
                        float C0 = 0.f, C1 = 0.f, C2 = 0.f;
                        #pragma unroll
                        for (int a = 0; a < 2; a++) {
                            const float v0 = __ldg(w3 + c * 9 + (1 + a) * 3 + 0);
                            const float v1 = __ldg(w3 + c * 9 + (1 + a) * 3 + 1);
                            const float v2 = __ldg(w3 + c * 9 + (1 + a) * 3 + 2);
                            C0 += v0 + v1; C1 += v0 + v1 + v2; C2 += v1 + v2;
                        }
                        #pragma unroll
                        for (int t = 0; t < 4; t++) {
                            const int q   = q0 + t;
                            const int cat = (q == 0) ? 0 : ((q == 251) ? 2 : 1);
                            wsv[t] = (cat == 0) ? C0 : ((cat == 2) ? C2 : C1);
                        }
                    }
                    #pragma unroll
                    for (int t = 0; t < 4; t++) {
                        gsum = fmaf(fast_gelu(acc[sret][t] + bias),
                                    wsv[t], gsum);
                        acc[sret][t] = 0.f;
                    }
                }
            }
        }

        // warp reduce (fixed order -> deterministic)
        #pragma unroll
        for (int o = 16; o; o >>= 1)
            gsum += __shfl_xor_sync(0xffffffffu, gsum, o);

        int mlp_b = -1;
        if (lane == 0) {
            g_part[uc] = gsum;
            __threadfence();
            if (atomicAdd(&g_map_cnt[m], 1u) == 7u) {
                __threadfence();               // acquire other warps' partials
                float s = 0.f;
                #pragma unroll
                for (int k = 0; k < 8; k++) s += g_part[m * 8 + k];  // fixed order
                g_sums[m] = s;
                __threadfence();
                if (atomicAdd(&g_batch_cnt[b], 1u) == 24u) mlp_b = b;
            }
        }
        mlp_b = __shfl_sync(0xffffffffu, mlp_b, 0);
        if (mlp_b >= 0)
            warp_mlp(mlp_b, lane, sc, fc1w, fc1b, fc2w, fc2b, out_idx);
    }

    // ===================== phase 2: gather warp-units =====================
    // 6400 units = 32 batches x 25 maps x 8 octants, batch-ordered.
    while (true) {
        int g;
        if (lane == 0) g = (int)atomicAdd(&g_gather_ctr, 1u);
        g = __shfl_sync(0xffffffffu, g, 0);
        if (g >= 6400) break;
        const int b   = g / 200;
        const int rem = g % 200;
        const int r   = rem >> 3;
        const int oct = rem & 7;

        if (lane == 0) {
            while (g_batch_ready[b] == 0) __nanosleep(64);
        }
        __syncwarp();
        __threadfence();   // acquire gate/chan

        const int   ch = g_chan[b * 25 + r];
        const float gt = g_gate[b * 25 + r];

        const float4* __restrict__ src =
            reinterpret_cast<const float4*>(x + ((size_t)b * 25 + ch) * 65536);
        float* dbase;
        if (r < 10) dbase = out + ((size_t)b * 10 + r) * 65536;
        else        dbase = out + 20971520ull + ((size_t)b * 15 + (r - 10)) * 65536;
        float4* __restrict__ dst = reinterpret_cast<float4*>(dbase);

        const int base = oct * 2048 + lane;   // 2048 float4 per octant
        #pragma unroll
        for (int blk = 0; blk < 4; blk++) {
            float4 v[16];
            #pragma unroll
            for (int k = 0; k < 16; k++)
                v[k] = __ldcs(&src[base + (blk * 16 + k) * 32]);
            #pragma unroll
            for (int k = 0; k < 16; k++) {
                v[k].x *= gt; v[k].y *= gt; v[k].z *= gt; v[k].w *= gt;
                __stcs(&dst[base + (blk * 16 + k) * 32], v[k]);
            }
        }
    }

    // ===================== exit: last warp resets queues =====================
    {
        int is_last = 0;
        if (lane == 0) {
            __threadfence();
            unsigned v = atomicAdd(&g_exit_ctr, 1u);
            is_last = (v == gridDim.x * 8u - 1u);
        }
        is_last = __shfl_sync(0xffffffffu, is_last, 0);
        if (is_last) {
            for (int i = lane; i < 800; i += 32) g_map_cnt[i] = 0;
            g_batch_cnt[lane]   = 0;            // lane < 32
            g_batch_ready[lane] = 0;
            if (lane == 0) {
                g_conv_ctr   = 0;
                g_gather_ctr = 0;
                g_exit_ctr   = 0;
            }
            __threadfence();
        }
    }
}

// =========================================================================
extern "C" void kernel_launch(void* const* d_in, const int* in_sizes, int n_in,
                              void* d_out, int out_size)
{
    const float* x    = (const float*)d_in[0];
    const float* w7   = (const float*)d_in[1];
    const float* b7   = (const float*)d_in[2];
    const float* w3   = (const float*)d_in[3];
    const float* fc1w = (const float*)d_in[4];
    const float* fc1b = (const float*)d_in[5];
    const float* fc2w = (const float*)d_in[6];
    const float* fc2b = (const float*)d_in[7];
    float* out = (float*)d_out;

    mega_kernel<<<296, 256>>>(x, w7, b7, w3, fc1w, fc1b, fc2w, fc2b, out);
}

// round 17
// speedup vs baseline: 1.3910x; 1.0083x over previous
#include <cuda_runtime.h>
#include <math.h>

// ---------------- device scratch (no allocations allowed) ----------------
static __device__ float         g_part[800 * 14];
static __device__ float         g_sums[800];
static __device__ float         g_gate[800];
static __device__ int           g_chan[800];
static __device__ unsigned int  g_conv_ctr   = 0;
static __device__ unsigned int  g_gather_ctr = 0;
static __device__ unsigned int  g_exit_ctr   = 0;
static __device__ unsigned int  g_map_cnt[800];
static __device__ unsigned int  g_batch_cnt[32];
static __device__ volatile int  g_batch_ready[32];

// Fast exact-form GELU: A&S 7.1.25 3-term erf (max abs err ~2.5e-5).
__device__ __forceinline__ float fast_gelu(float h)
{
    const float az = fabsf(h) * 0.7071067811865476f;
    const float t  = __fdividef(1.0f, fmaf(0.47047f, az, 1.0f));
    float p = fmaf(0.7478556f, t, -0.0958798f);
    p = fmaf(p, t, 0.3480242f);
    const float ex = __expf(-0.5f * h * h);
    float er = fmaf(-p * t, ex, 1.0f);
    er = copysignf(er, h);
    return 0.5f * h * (1.0f + er);
}

// Warp-local MLP + sigmoid + gate + stable top-k for one batch.
__device__ __forceinline__ void warp_mlp(int bb, int lane, float* sc,
                                         const float* __restrict__ fc1w,
                                         const float* __restrict__ fc1b,
                                         const float* __restrict__ fc2w,
                                         const float* __restrict__ fc2b,
                                         float* __restrict__ out_idx)
{
    __threadfence();    // acquire g_sums written by other warps
    if (lane < 25) sc[lane] = g_sums[bb * 25 + lane] * (1.0f / 63504.0f);
    __syncwarp();
    #pragma unroll
    for (int rep = 0; rep < 2; rep++) {
        const int j = lane + rep * 32;
        if (j < 50) {
            float v = __ldg(fc1b + j);
            #pragma unroll
            for (int cc = 0; cc < 25; cc++)
                v = fmaf(sc[cc], __ldg(fc1w + j * 25 + cc), v);
            sc[25 + j] = v > 0.f ? v : 0.f;
        }
    }
    __syncwarp();
    if (lane < 25) {
        float z = __ldg(fc2b + lane);
        #pragma unroll
        for (int j = 0; j < 50; j++)
            z = fmaf(sc[25 + j], __ldg(fc2w + lane * 50 + j), z);
        sc[lane] = 1.0f / (1.0f + expf(-z));
    }
    __syncwarp();
    if (lane < 25) {
        const float sv = sc[lane];
        int rank = 0;
        #pragma unroll
        for (int o = 0; o < 25; o++) {
            const float ov = sc[o];
            rank += (ov > sv) || (ov == sv && o < lane);
        }
        const float s2 = sv * sv;
        g_chan[bb * 25 + rank]  = lane;
        g_gate[bb * 25 + rank]  = s2 / (s2 + 1e-8f);
        out_idx[bb * 25 + rank] = (float)lane;
        __threadfence();    // release before ready flag
    }
    __syncwarp();
    if (lane == 0) g_batch_ready[bb] = 1;
}

// ---- conv inner-loop macros ----
// Clamped variants (prologue / tail rows may fall outside [0,255]).
#define ISSUE_LOADS(RN)                                                    \
    const int  rn   = (RN);                                                \
    const bool rokn = ((unsigned)rn < 256u);                               \
    const int  rcn  = rokn ? rn : (rn < 0 ? 0 : 255);                      \
    const float* __restrict__ rowp = xm + rcn * 256;                       \
    const float  nxl = rowp[offL];                                         \
    const float4 nv0 = *reinterpret_cast<const float4*>(rowp + q0);        \
    const float4 nv1 = *reinterpret_cast<const float4*>(rowp + q0 + 4);    \
    const float  nxr = rowp[offR];

#define COMMIT_BUF()                                                       \
    buf[0] = (rokn && okL) ? nxl : 0.f;                                    \
    buf[1] = rokn ? nv0.x : 0.f;  buf[2] = rokn ? nv0.y : 0.f;             \
    buf[3] = rokn ? nv0.z : 0.f;  buf[4] = rokn ? nv0.w : 0.f;             \
    buf[5] = rokn ? nv1.x : 0.f;  buf[6] = rokn ? nv1.y : 0.f;             \
    buf[7] = rokn ? nv1.z : 0.f;  buf[8] = rokn ? nv1.w : 0.f;             \
    buf[9] = (rokn && okR) ? nxr : 0.f;

// Unclamped FAST variants: rows provably in [0,255] (warmup + main).
#define ISSUE_LOADS_FAST(RN)                                               \
    const float* __restrict__ rowp = xm + (RN) * 256;                      \
    const float  nxl = rowp[offL];                                         \
    const float4 nv0 = *reinterpret_cast<const float4*>(rowp + q0);        \
    const float4 nv1 = *reinterpret_cast<const float4*>(rowp + q0 + 4);    \
    const float  nxr = rowp[offR];

#define COMMIT_BUF_FAST()                                                  \
    buf[0] = okL ? nxl : 0.f;                                              \
    buf[1] = nv0.x;  buf[2] = nv0.y;  buf[3] = nv0.z;  buf[4] = nv0.w;     \
    buf[5] = nv1.x;  buf[6] = nv1.y;  buf[7] = nv1.z;  buf[8] = nv1.w;     \
    buf[9] = okR ? nxr : 0.f;

#define TAP_ROW(S, A)                                                      \
    _Pragma("unroll")                                                      \
    for (int dx = 0; dx < 7; dx++) {                                       \
        const float wk = w[(A) * 7 + dx];                                  \
        acc[S][0] = fmaf(buf[dx],     wk, acc[S][0]);                      \
        acc[S][1] = fmaf(buf[dx + 1], wk, acc[S][1]);                      \
        acc[S][2] = fmaf(buf[dx + 2], wk, acc[S][2]);                      \
        acc[S][3] = fmaf(buf[dx + 3], wk, acc[S][3]);                      \
    }

#define RETIRE4(S, WSV)                                                    \
    _Pragma("unroll")                                                      \
    for (int t = 0; t < 4; t++) {                                          \
        gsum = fmaf(fast_gelu(acc[S][t] + bias), (WSV)[t], gsum);          \
        acc[S][t] = 0.f;                                                   \
    }

// =========================================================================
// Persistent warp-autonomous mega-kernel, two-phase.
// Conv: 11200 warp-units (800 maps x 7 row-bands(36) x 2 col-halves):
// finer units cut queue quantization from 11% to 5.7%. Peeled ring loop
// (warmup 7 / main 4x7+1 / tail 6); main path fully unguarded.
// =========================================================================
__global__ __launch_bounds__(256, 2)
void mega_kernel(const float* __restrict__ x,
                 const float* __restrict__ w7,
                 const float* __restrict__ b7,
                 const float* __restrict__ w3,
                 const float* __restrict__ fc1w,
                 const float* __restrict__ fc1b,
                 const float* __restrict__ fc2w,
                 const float* __restrict__ fc2b,
                 float* __restrict__ out)
{
    __shared__ float wsch[8][80];
    const int lane = threadIdx.x & 31;
    const int wid  = threadIdx.x >> 5;
    float* sc = wsch[wid];
    float* __restrict__ out_idx = out + 52428800ull;

    // ===================== phase 1: conv warp-units =====================
    while (true) {
        int uc;
        if (lane == 0) uc = (int)atomicAdd(&g_conv_ctr, 1u);
        uc = __shfl_sync(0xffffffffu, uc, 0);
        if (uc >= 11200) break;

        const int m    = uc / 14;       // map (batch-major order)
        const int sub  = uc % 14;
        const int band = sub >> 1;      // 0..6
        const int half = sub & 1;
        const int c    = m % 25;
        const int b    = m / 25;
        const int cg   = half * 32 + lane;   // 0..63, active < 63

        float gsum = 0.f;

        if (cg < 63) {
            float w[49];
            #pragma unroll
            for (int k = 0; k < 49; k++) w[k] = __ldg(w7 + c * 49 + k);
            const float bias = __ldg(b7 + c);

            float M0 = 0.f, M1 = 0.f, M2 = 0.f;
            #pragma unroll
            for (int a = 0; a < 3; a++) {
                const float v0 = __ldg(w3 + c * 9 + a * 3 + 0);
                const float v1 = __ldg(w3 + c * 9 + a * 3 + 1);
                const float v2 = __ldg(w3 + c * 9 + a * 3 + 2);
                M0 += v0 + v1; M1 += v0 + v1 + v2; M2 += v1 + v2;
            }
            const int q0 = cg * 4;
            float wv1[4];
            #pragma unroll
            for (int t = 0; t < 4; t++) {
                const int q   = q0 + t;
                const int cat = (q == 0) ? 0 : ((q == 251) ? 2 : 1);
                wv1[t] = (cat == 0) ? M0 : ((cat == 2) ? M2 : M1);
            }

            const bool okL  = (q0 > 0);
            const bool okR  = (q0 + 8 < 256);
            const int  offL = okL ? (q0 - 1) : 0;
            const int  offR = okR ? (q0 + 8) : 255;
            const int  lo   = band * 36;            // outputs lo..lo+35
            const float* __restrict__ xm = x + (size_t)m * 65536;

            float buf[10];
            {   // prologue: row lo-1 into buf (clamped: lo==0 case)
                ISSUE_LOADS(lo - 1)
                COMMIT_BUF()
            }

            float acc[7][4];
            #pragma unroll
            for (int s = 0; s < 7; s++)
                #pragma unroll
                for (int t = 0; t < 4; t++) acc[s][t] = 0.f;

            // ---- warmup: j=0..6, buf holds row lo-1+j, taps a<=j ----
            #pragma unroll
            for (int j = 0; j <= 6; j++) {
                ISSUE_LOADS_FAST(lo + j)       // rows lo..lo+6, always valid
                #pragma unroll
                for (int a = 0; a <= j; a++) {
                    TAP_ROW((j - a) % 7, a)
                }
                if (j == 6) {
                    // retire output i = lo (slot 0); edge iff lo == 0
                    float wsv[4];
                    #pragma unroll
                    for (int t = 0; t < 4; t++) wsv[t] = wv1[t];
                    if (lo == 0) {
                        float C0 = 0.f, C1 = 0.f, C2 = 0.f;
                        #pragma unroll
                        for (int a = 0; a < 2; a++) {
                            const float v0 = __ldg(w3 + c * 9 + a * 3 + 0);
                            const float v1 = __ldg(w3 + c * 9 + a * 3 + 1);
                            const float v2 = __ldg(w3 + c * 9 + a * 3 + 2);
                            C0 += v0 + v1; C1 += v0 + v1 + v2; C2 += v1 + v2;
                        }
                        #pragma unroll
                        for (int t = 0; t < 4; t++) {
                            const int q   = q0 + t;
                            const int cat = (q == 0) ? 0 : ((q == 251) ? 2 : 1);
                            wsv[t] = (cat == 0) ? C0 : ((cat == 2) ? C2 : C1);
                        }
                    }
                    RETIRE4(0, wsv)
                }
                COMMIT_BUF_FAST()
            }

            // ---- main: rows lo+6+it*7+u (phase u), retire lo+1+it*7+u ----
            // rows lo+6..lo+33; all interior (>=6, <=249) -> unguarded
            for (int it = 0; it < 4; ++it) {
                #pragma unroll
                for (int u = 0; u < 7; u++) {
                    ISSUE_LOADS_FAST(lo + 7 + it * 7 + u)   // <= lo+34 <= 250
                    #pragma unroll
                    for (int a = 0; a < 7; a++) {
                        TAP_ROW((u - a + 7) % 7, a)
                    }
                    RETIRE4((u + 1) % 7, wv1)               // lo+1..lo+28
                    COMMIT_BUF_FAST()
                }
            }
            // extra main iteration: row lo+34 (phase 0), retire lo+29
            {
                ISSUE_LOADS_FAST(lo + 35)                   // <= 251
                #pragma unroll
                for (int a = 0; a < 7; a++) {
                    TAP_ROW((0 - a + 7) % 7, a)
                }
                RETIRE4(1, wv1)
                COMMIT_BUF_FAST()
            }

            // ---- tail: d=0..5, buf holds row lo+35+d (phase (1+d)%7),
            //      taps a>=d+1, retire lo+30+d at slot (2+d)%7 ----
            #pragma unroll
            for (int d = 0; d < 6; d++) {
                if (d < 5) {
                    ISSUE_LOADS(lo + 36 + d)   // may reach 256 -> clamped
                    #pragma unroll
                    for (int a = d + 1; a < 7; a++) {
                        TAP_ROW((1 + d - a + 7) % 7, a)
                    }
                    RETIRE4((2 + d) % 7, wv1)  // lo+30..lo+34, interior
                    COMMIT_BUF()
                } else {
                    // d == 5: last row, no prefetch; retire i = lo+35
                    #pragma unroll
                    for (int a = 6; a < 7; a++) {
                        TAP_ROW((1 + d - a + 7) % 7, a)
                    }
                    const int i = lo + 35;
                    float wsv[4];
                    #pragma unroll
                    for (int t = 0; t < 4; t++) wsv[t] = wv1[t];
                    if (i == 251) {
                        float C0 = 0.f, C1 = 0.f, C2 = 0.f;
                        #pragma unroll
                        for (int a = 0; a < 2; a++) {
                            const float v0 = __ldg(w3 + c * 9 + (1 + a) * 3 + 0);
                            const float v1 = __ldg(w3 + c * 9 + (1 + a) * 3 + 1);
                            const float v2 = __ldg(w3 + c * 9 + (1 + a) * 3 + 2);
                            C0 += v0 + v1; C1 += v0 + v1 + v2; C2 += v1 + v2;
                        }
                        #pragma unroll
                        for (int t = 0; t < 4; t++) {
                            const int q   = q0 + t;
                            const int cat = (q == 0) ? 0 : ((q == 251) ? 2 : 1);
                            wsv[t] = (cat == 0) ? C0 : ((cat == 2) ? C2 : C1);
                        }
                    }
                    RETIRE4((2 + d) % 7, wsv)
                }
            }
        }

        // warp reduce (fixed order -> deterministic)
        #pragma unroll
        for (int o = 16; o; o >>= 1)
            gsum += __shfl_xor_sync(0xffffffffu, gsum, o);

        int mlp_b = -1;
        if (lane == 0) {
            g_part[uc] = gsum;
            __threadfence();
            if (atomicAdd(&g_map_cnt[m], 1u) == 13u) {
                __threadfence();               // acquire other warps' partials
                float s = 0.f;
                #pragma unroll
                for (int k = 0; k < 14; k++) s += g_part[m * 14 + k];  // fixed order
                g_sums[m] = s;
                __threadfence();
                if (atomicAdd(&g_batch_cnt[b], 1u) == 24u) mlp_b = b;
            }
        }
        mlp_b = __shfl_sync(0xffffffffu, mlp_b, 0);
        if (mlp_b >= 0)
            warp_mlp(mlp_b, lane, sc, fc1w, fc1b, fc2w, fc2b, out_idx);
    }

    // ===================== phase 2: gather warp-units =====================
    // 6400 units = 32 batches x 25 maps x 8 octants, batch-ordered.
    while (true) {
        int g;
        if (lane == 0) g = (int)atomicAdd(&g_gather_ctr, 1u);
        g = __shfl_sync(0xffffffffu, g, 0);
        if (g >= 6400) break;
        const int b   = g / 200;
        const int rem = g % 200;
        const int r   = rem >> 3;
        const int oct = rem & 7;

        if (lane == 0) {
            while (g_batch_ready[b] == 0) __nanosleep(64);
        }
        __syncwarp();
        __threadfence();   // acquire gate/chan

        const int   ch = g_chan[b * 25 + r];
        const float gt = g_gate[b * 25 + r];

        const float4* __restrict__ src =
            reinterpret_cast<const float4*>(x + ((size_t)b * 25 + ch) * 65536);
        float* dbase;
        if (r < 10) dbase = out + ((size_t)b * 10 + r) * 65536;
        else        dbase = out + 20971520ull + ((size_t)b * 15 + (r - 10)) * 65536;
        float4* __restrict__ dst = reinterpret_cast<float4*>(dbase);

        const int base = oct * 2048 + lane;   // 2048 float4 per octant
        #pragma unroll
        for (int blk = 0; blk < 4; blk++) {
            float4 v[16];
            #pragma unroll
            for (int k = 0; k < 16; k++)
                v[k] = __ldcs(&src[base + (blk * 16 + k) * 32]);
            #pragma unroll
            for (int k = 0; k < 16; k++) {
                v[k].x *= gt; v[k].y *= gt; v[k].z *= gt; v[k].w *= gt;
                __stcs(&dst[base + (blk * 16 + k) * 32], v[k]);
            }
        }
    }

    // ===================== exit: last warp resets queues =====================
    {
        int is_last = 0;
        if (lane == 0) {
            __threadfence();
            unsigned v = atomicAdd(&g_exit_ctr, 1u);
            is_last = (v == gridDim.x * 8u - 1u);
        }
        is_last = __shfl_sync(0xffffffffu, is_last, 0);
        if (is_last) {
            for (int i = lane; i < 800; i += 32) g_map_cnt[i] = 0;
            g_batch_cnt[lane]   = 0;            // lane < 32
            g_batch_ready[lane] = 0;
            if (lane == 0) {
                g_conv_ctr   = 0;
                g_gather_ctr = 0;
                g_exit_ctr   = 0;
            }
            __threadfence();
        }
    }
}

// =========================================================================
extern "C" void kernel_launch(void* const* d_in, const int* in_sizes, int n_in,
                              void* d_out, int out_size)
{
    const float* x    = (const float*)d_in[0];
    const float* w7   = (const float*)d_in[1];
    const float* b7   = (const float*)d_in[2];
    const float* w3   = (const float*)d_in[3];
    const float* fc1w = (const float*)d_in[4];
    const float* fc1b = (const float*)d_in[5];
    const float* fc2w = (const float*)d_in[6];
    const float* fc2b = (const float*)d_in[7];
    float* out = (float*)d_out;

    mega_kernel<<<296, 256>>>(x, w7, b7, w3, fc1w, fc1b, fc2w, fc2b, out);
}